// round 11
// baseline (speedup 1.0000x reference)
#include <cuda_runtime.h>

__constant__ float cW1[20 * 64];

// Insert e into sorted (desc) top-4 registers t0>=t1>=t2>=t3.
__device__ __forceinline__ void ins4(float e, float& t0, float& t1, float& t2, float& t3)
{
    float c = e;
    float n0 = fmaxf(t0, c); c = fminf(t0, c);
    float n1 = fmaxf(t1, c); c = fminf(t1, c);
    float n2 = fmaxf(t2, c); c = fminf(t2, c);
    t3 = fmaxf(t3, c);
    t0 = n0; t1 = n1; t2 = n2;
}

__device__ __forceinline__ void acc_one(float v, float& s,
                                        float& t0, float& t1, float& t2, float& t3)
{
    float e = __expf(v);
    s += e;
    ins4(e, t0, t1, t2, t3);
}

// Block = 128 threads (4 warps) = 32 rows.
//  Phase A: thread (row=tid>>2, g=tid&3): top4+sum for ONE group of 33 (conflict-free LDS).
//           Stats -> sStat pitch 20 (16B-aligned rows, 5l mod 8 enumerates bank-quads).
//  Phase B: warp w computes hidden [16w,16w+16) for row=lane; W1 from __constant__
//           (warp-uniform -> constant port, off L1tex). b1/W2 stay in smem (uniform LDS).
//  Phase C: coalesced float4: out = scores + sum of 4 partials (b2 folded into warp 0).
__global__ __launch_bounds__(128, 9)
void lqe_kernel(const float* __restrict__ scores,
                const float* __restrict__ corners,
                const float* __restrict__ gb1,
                const float* __restrict__ gW2,
                const float* __restrict__ gb2,
                float* __restrict__ out,
                int rows)
{
    __shared__ __align__(16) float sC[32 * 132];     // 16896 B
    __shared__ __align__(16) float sB1[64];
    __shared__ __align__(16) float sW2[64];
    __shared__ __align__(16) float sStat[32 * 20];   // 2560 B, pitch 20
    __shared__ float sQp[4 * 32];                    // per-warp partial q
    __shared__ float sB2;

    const int tid  = threadIdx.x;
    const int row0 = blockIdx.x * 32;
    const int nr   = min(32, rows - row0);

    // ---------------- stage corners (coalesced float4) ----------------
    {
        const float4* src = (const float4*)(corners + (size_t)row0 * 132);
        float4* dst = (float4*)sC;
        if (nr == 32) {                       // 1056 float4 = 8.25 * 128
            #pragma unroll
            for (int j = 0; j < 8; j++) dst[j * 128 + tid] = src[j * 128 + tid];
            if (tid < 32) dst[1024 + tid] = src[1024 + tid];
        } else {
            int n4 = nr * 33;
            for (int i = tid; i < n4; i += 128) dst[i] = src[i];
        }
    }
    // ---------------- stage small weights ----------------
    {
        if (tid < 64)       sB1[tid] = gb1[tid];
        else if (tid < 128) sW2[tid - 64] = gW2[tid - 64];
        if (tid == 0)       sB2 = gb2[0];
    }
    __syncthreads();

    // ---------------- Phase A: one group of 33 per thread ----------------
    {
        const int lrow = tid >> 2;
        const int g    = tid & 3;
        if (lrow < nr) {
            const float* base = sC + lrow * 132 + 33 * g;
            float s = 0.f;
            float t0 = 0.f, t1 = 0.f, t2 = 0.f, t3 = 0.f;
            #pragma unroll
            for (int k = 0; k < 33; k++)
                acc_one(base[k], s, t0, t1, t2, t3);

            float inv = __frcp_rn(s);
            float p0 = t0 * inv, p1 = t1 * inv, p2 = t2 * inv, p3 = t3 * inv;
            float mean = 0.25f * ((p0 + p1) + (p2 + p3));

            float* so = sStat + lrow * 20 + 5 * g;
            so[0] = p0; so[1] = p1; so[2] = p2; so[3] = p3; so[4] = mean;
        }
    }
    __syncthreads();

    // ---------------- Phase B: MLP (warp w -> hidden [16w,16w+16), row=lane) ----------------
    {
        const int warp = tid >> 5;
        const int lane = tid & 31;

        float st[20];
        {
            const float* sr = sStat + lane * 20;   // 16B-aligned, conflict-free LDS.128
            float4 a0 = *(const float4*)(sr + 0);
            float4 a1 = *(const float4*)(sr + 4);
            float4 a2 = *(const float4*)(sr + 8);
            float4 a3 = *(const float4*)(sr + 12);
            float4 a4 = *(const float4*)(sr + 16);
            st[0]  = a0.x; st[1]  = a0.y; st[2]  = a0.z; st[3]  = a0.w;
            st[4]  = a1.x; st[5]  = a1.y; st[6]  = a1.z; st[7]  = a1.w;
            st[8]  = a2.x; st[9]  = a2.y; st[10] = a2.z; st[11] = a2.w;
            st[12] = a3.x; st[13] = a3.y; st[14] = a3.z; st[15] = a3.w;
            st[16] = a4.x; st[17] = a4.y; st[18] = a4.z; st[19] = a4.w;
        }

        float q = (warp == 0) ? sB2 : 0.f;
        #pragma unroll
        for (int pass = 0; pass < 2; pass++) {
            const int h0 = warp * 16 + pass * 8;   // warp-uniform
            float acc[8];
            {
                float4 ba = *(const float4*)(sB1 + h0);
                float4 bb = *(const float4*)(sB1 + h0 + 4);
                acc[0] = ba.x; acc[1] = ba.y; acc[2] = ba.z; acc[3] = ba.w;
                acc[4] = bb.x; acc[5] = bb.y; acc[6] = bb.z; acc[7] = bb.w;
            }
            #pragma unroll
            for (int d = 0; d < 20; d++) {
                float sd = st[d];
                float4 wa = *(const float4*)&cW1[d * 64 + h0];       // constant port
                float4 wb = *(const float4*)&cW1[d * 64 + h0 + 4];
                acc[0] += sd * wa.x; acc[1] += sd * wa.y;
                acc[2] += sd * wa.z; acc[3] += sd * wa.w;
                acc[4] += sd * wb.x; acc[5] += sd * wb.y;
                acc[6] += sd * wb.z; acc[7] += sd * wb.w;
            }
            {
                float4 wa = *(const float4*)(sW2 + h0);
                float4 wb = *(const float4*)(sW2 + h0 + 4);
                q += fmaxf(acc[0], 0.f) * wa.x;
                q += fmaxf(acc[1], 0.f) * wa.y;
                q += fmaxf(acc[2], 0.f) * wa.z;
                q += fmaxf(acc[3], 0.f) * wa.w;
                q += fmaxf(acc[4], 0.f) * wb.x;
                q += fmaxf(acc[5], 0.f) * wb.y;
                q += fmaxf(acc[6], 0.f) * wb.z;
                q += fmaxf(acc[7], 0.f) * wb.w;
            }
        }
        sQp[warp * 32 + lane] = q;
    }
    __syncthreads();

    // ---------------- Phase C: out = scores + q ----------------
    {
        const float4* s4 = (const float4*)(scores + (size_t)row0 * 80);
        float4*       o4 = (float4*)(out + (size_t)row0 * 80);
        if (nr == 32) {                       // 640 float4 = 5 * 128
            #pragma unroll
            for (int j = 0; j < 5; j++) {
                int i = j * 128 + tid;
                int r = i / 20;
                float qv = (sQp[r] + sQp[32 + r]) + (sQp[64 + r] + sQp[96 + r]);
                float4 v = s4[i];
                v.x += qv; v.y += qv; v.z += qv; v.w += qv;
                o4[i] = v;
            }
        } else {
            int n4 = nr * 20;
            for (int i = tid; i < n4; i += 128) {
                int r = i / 20;
                float qv = (sQp[r] + sQp[32 + r]) + (sQp[64 + r] + sQp[96 + r]);
                float4 v = s4[i];
                v.x += qv; v.y += qv; v.z += qv; v.w += qv;
                o4[i] = v;
            }
        }
    }
}

extern "C" void kernel_launch(void* const* d_in, const int* in_sizes, int n_in,
                              void* d_out, int out_size) {
    const float* scores  = (const float*)d_in[0];
    const float* corners = (const float*)d_in[1];
    const float* b1      = (const float*)d_in[3];
    const float* W2      = (const float*)d_in[4];
    const float* b2      = (const float*)d_in[5];
    float* out = (float*)d_out;

    cudaMemcpyToSymbolAsync(cW1, d_in[2], 20 * 64 * sizeof(float), 0,
                            cudaMemcpyDeviceToDevice, 0);

    int rows = in_sizes[0] / 80;              // B*L
    int blocks = (rows + 31) / 32;
    lqe_kernel<<<blocks, 128>>>(scores, corners, b1, W2, b2, out, rows);
}

// round 12
// speedup vs baseline: 5.0098x; 5.0098x over previous
#include <cuda_runtime.h>
#include <cstdint>

__device__ __forceinline__ uint32_t smem_u32(const void* p) {
    uint32_t a;
    asm("{ .reg .u64 t; cvta.to.shared.u64 t, %1; cvt.u32.u64 %0, t; }"
        : "=r"(a) : "l"(p));
    return a;
}

__device__ __forceinline__ void mbar_init(uint32_t mbar, uint32_t cnt) {
    asm volatile("mbarrier.init.shared.b64 [%0], %1;" :: "r"(mbar), "r"(cnt) : "memory");
}

__device__ __forceinline__ void mbar_expect_tx(uint32_t mbar, uint32_t bytes) {
    asm volatile("mbarrier.arrive.expect_tx.shared.b64 _, [%0], %1;"
                 :: "r"(mbar), "r"(bytes) : "memory");
}

__device__ __forceinline__ void bulk_g2s(uint32_t dst, const void* src,
                                         uint32_t bytes, uint32_t mbar) {
    asm volatile(
        "cp.async.bulk.shared::cluster.global.mbarrier::complete_tx::bytes "
        "[%0], [%1], %2, [%3];"
        :: "r"(dst), "l"(src), "r"(bytes), "r"(mbar) : "memory");
}

__device__ __forceinline__ void mbar_wait(uint32_t mbar, uint32_t parity) {
    asm volatile(
        "{\n\t"
        ".reg .pred P;\n\t"
        "W%=:\n\t"
        "mbarrier.try_wait.parity.acquire.cta.shared::cta.b64 P, [%0], %1, 0x989680;\n\t"
        "@!P bra W%=;\n\t"
        "}"
        :: "r"(mbar), "r"(parity) : "memory");
}

// Insert e into sorted (desc) top-4 registers t0>=t1>=t2>=t3.
__device__ __forceinline__ void ins4(float e, float& t0, float& t1, float& t2, float& t3)
{
    float c = e;
    float n0 = fmaxf(t0, c); c = fminf(t0, c);
    float n1 = fmaxf(t1, c); c = fminf(t1, c);
    float n2 = fmaxf(t2, c); c = fminf(t2, c);
    t3 = fmaxf(t3, c);
    t0 = n0; t1 = n1; t2 = n2;
}

__device__ __forceinline__ void acc_one(float v, float& s,
                                        float& t0, float& t1, float& t2, float& t3)
{
    float e = __expf(v);
    s += e;
    ins4(e, t0, t1, t2, t3);
}

// Block = 128 threads (4 warps) = 32 rows.
//  Stage:   cp.async.bulk GMEM->SMEM for the 32x132 corner tile (no LDG/STS round trip).
//  Phase A: thread (row=tid>>2, g=tid&3): top4+sum for ONE group of 33 (conflict-free LDS,
//           bank = (4r+g+k) mod 32 enumerates all banks). Stats -> sStat pitch 20.
//  Phase B: warp w computes hidden [16w,16w+16) for row=lane; weights via warp-uniform
//           __ldg float4 (broadcast, L1-resident across blocks within the launch).
//  Phase C: coalesced float4: out = scores + sum of 4 partials (b2 folded into warp 0).
__global__ __launch_bounds__(128, 10)
void lqe_kernel(const float* __restrict__ scores,
                const float* __restrict__ corners,
                const float* __restrict__ gW1,
                const float* __restrict__ gb1,
                const float* __restrict__ gW2,
                const float* __restrict__ gb2,
                float* __restrict__ out,
                int rows)
{
    __shared__ __align__(16) float sC[32 * 132];     // 16896 B
    __shared__ __align__(16) float sStat[32 * 20];   //  2560 B, pitch 20
    __shared__ float sQp[4 * 32];                    // per-warp partial q
    __shared__ __align__(8) unsigned long long smbar;

    const int tid  = threadIdx.x;
    const int row0 = blockIdx.x * 32;
    const int nr   = min(32, rows - row0);

    // ---------------- stage corners ----------------
    if (nr == 32) {
        const uint32_t mb = smem_u32(&smbar);
        if (tid == 0) mbar_init(mb, 1);
        __syncthreads();
        if (tid == 0) {
            mbar_expect_tx(mb, 32 * 132 * 4);
            bulk_g2s(smem_u32(sC), corners + (size_t)row0 * 132, 32 * 132 * 4, mb);
        }
        mbar_wait(mb, 0);
    } else {
        const float4* src = (const float4*)(corners + (size_t)row0 * 132);
        float4* dst = (float4*)sC;
        int n4 = nr * 33;
        for (int i = tid; i < n4; i += 128) dst[i] = src[i];
        __syncthreads();
    }

    // ---------------- Phase A: one group of 33 per thread ----------------
    {
        const int lrow = tid >> 2;
        const int g    = tid & 3;
        if (lrow < nr) {
            const float* base = sC + lrow * 132 + 33 * g;
            float s = 0.f;
            float t0 = 0.f, t1 = 0.f, t2 = 0.f, t3 = 0.f;
            #pragma unroll
            for (int k = 0; k < 33; k++)
                acc_one(base[k], s, t0, t1, t2, t3);

            float inv = __frcp_rn(s);
            float p0 = t0 * inv, p1 = t1 * inv, p2 = t2 * inv, p3 = t3 * inv;
            float mean = 0.25f * ((p0 + p1) + (p2 + p3));

            float* so = sStat + lrow * 20 + 5 * g;
            so[0] = p0; so[1] = p1; so[2] = p2; so[3] = p3; so[4] = mean;
        }
    }
    __syncthreads();

    // ---------------- Phase B: MLP (warp w -> hidden [16w,16w+16), row=lane) ----------------
    {
        const int warp = tid >> 5;
        const int lane = tid & 31;

        float st[20];
        {
            const float* sr = sStat + lane * 20;   // 16B-aligned, conflict-free LDS.128
            float4 a0 = *(const float4*)(sr + 0);
            float4 a1 = *(const float4*)(sr + 4);
            float4 a2 = *(const float4*)(sr + 8);
            float4 a3 = *(const float4*)(sr + 12);
            float4 a4 = *(const float4*)(sr + 16);
            st[0]  = a0.x; st[1]  = a0.y; st[2]  = a0.z; st[3]  = a0.w;
            st[4]  = a1.x; st[5]  = a1.y; st[6]  = a1.z; st[7]  = a1.w;
            st[8]  = a2.x; st[9]  = a2.y; st[10] = a2.z; st[11] = a2.w;
            st[12] = a3.x; st[13] = a3.y; st[14] = a3.z; st[15] = a3.w;
            st[16] = a4.x; st[17] = a4.y; st[18] = a4.z; st[19] = a4.w;
        }

        float q = (warp == 0) ? __ldg(gb2) : 0.f;
        #pragma unroll
        for (int pass = 0; pass < 2; pass++) {
            const int h0 = warp * 16 + pass * 8;   // warp-uniform
            float acc[8];
            {
                float4 ba = __ldg((const float4*)(gb1 + h0));
                float4 bb = __ldg((const float4*)(gb1 + h0 + 4));
                acc[0] = ba.x; acc[1] = ba.y; acc[2] = ba.z; acc[3] = ba.w;
                acc[4] = bb.x; acc[5] = bb.y; acc[6] = bb.z; acc[7] = bb.w;
            }
            #pragma unroll
            for (int d = 0; d < 20; d++) {
                float sd = st[d];
                float4 wa = __ldg((const float4*)(gW1 + d * 64 + h0));     // broadcast
                float4 wb = __ldg((const float4*)(gW1 + d * 64 + h0 + 4));
                acc[0] += sd * wa.x; acc[1] += sd * wa.y;
                acc[2] += sd * wa.z; acc[3] += sd * wa.w;
                acc[4] += sd * wb.x; acc[5] += sd * wb.y;
                acc[6] += sd * wb.z; acc[7] += sd * wb.w;
            }
            {
                float4 wa = __ldg((const float4*)(gW2 + h0));
                float4 wb = __ldg((const float4*)(gW2 + h0 + 4));
                q += fmaxf(acc[0], 0.f) * wa.x;
                q += fmaxf(acc[1], 0.f) * wa.y;
                q += fmaxf(acc[2], 0.f) * wa.z;
                q += fmaxf(acc[3], 0.f) * wa.w;
                q += fmaxf(acc[4], 0.f) * wb.x;
                q += fmaxf(acc[5], 0.f) * wb.y;
                q += fmaxf(acc[6], 0.f) * wb.z;
                q += fmaxf(acc[7], 0.f) * wb.w;
            }
        }
        sQp[warp * 32 + lane] = q;
    }
    __syncthreads();

    // ---------------- Phase C: out = scores + q ----------------
    {
        const float4* s4 = (const float4*)(scores + (size_t)row0 * 80);
        float4*       o4 = (float4*)(out + (size_t)row0 * 80);
        if (nr == 32) {                       // 640 float4 = 5 * 128
            #pragma unroll
            for (int j = 0; j < 5; j++) {
                int i = j * 128 + tid;
                int r = i / 20;
                float qv = (sQp[r] + sQp[32 + r]) + (sQp[64 + r] + sQp[96 + r]);
                float4 v = s4[i];
                v.x += qv; v.y += qv; v.z += qv; v.w += qv;
                o4[i] = v;
            }
        } else {
            int n4 = nr * 20;
            for (int i = tid; i < n4; i += 128) {
                int r = i / 20;
                float qv = (sQp[r] + sQp[32 + r]) + (sQp[64 + r] + sQp[96 + r]);
                float4 v = s4[i];
                v.x += qv; v.y += qv; v.z += qv; v.w += qv;
                o4[i] = v;
            }
        }
    }
}

extern "C" void kernel_launch(void* const* d_in, const int* in_sizes, int n_in,
                              void* d_out, int out_size) {
    const float* scores  = (const float*)d_in[0];
    const float* corners = (const float*)d_in[1];
    const float* W1      = (const float*)d_in[2];
    const float* b1      = (const float*)d_in[3];
    const float* W2      = (const float*)d_in[4];
    const float* b2      = (const float*)d_in[5];
    float* out = (float*)d_out;

    int rows = in_sizes[0] / 80;              // B*L
    int blocks = (rows + 31) / 32;
    lqe_kernel<<<blocks, 128>>>(scores, corners, W1, b1, W2, b2, out, rows);
}

// round 13
// speedup vs baseline: 6.1051x; 1.2186x over previous
#include <cuda_runtime.h>

// Insert e into sorted (desc) top-4 registers t0>=t1>=t2>=t3.
__device__ __forceinline__ void ins4(float e, float& t0, float& t1, float& t2, float& t3)
{
    float c = e;
    float n0 = fmaxf(t0, c); c = fminf(t0, c);
    float n1 = fmaxf(t1, c); c = fminf(t1, c);
    float n2 = fmaxf(t2, c); c = fminf(t2, c);
    t3 = fmaxf(t3, c);
    t0 = n0; t1 = n1; t2 = n2;
}

__device__ __forceinline__ void acc_one(float v, float& s,
                                        float& t0, float& t1, float& t2, float& t3)
{
    float e = __expf(v);
    s += e;
    ins4(e, t0, t1, t2, t3);
}

__device__ __forceinline__ void ce(float& a, float& b) {
    float hi = fmaxf(a, b);
    float lo = fminf(a, b);
    a = hi; b = lo;
}

// Block = 256 threads (8 warps) = 64 rows.
//  Phase A: thread (row=tid>>2, g=tid&3): top4+sum for ONE group of 33, computed as two
//           independent halves (17/16) then merged -> 2x ILP on the insertion chain.
//           LDS bank = (4r+g+k) mod 32 conflict-free. Stats -> sStat pitch 20.
//  Phase B: warp w = (rowhalf = w>>2, hq = w&3): rows rowhalf*32+lane,
//           hidden [16hq, 16hq+16) in 2 passes of 8. Weights uniform smem LDS.128.
//  Phase C: coalesced float4: out = scores + sum of 4 hidden-quarter partials.
__global__ __launch_bounds__(256, 5)
void lqe_kernel(const float* __restrict__ scores,
                const float* __restrict__ corners,
                const float* __restrict__ gW1,
                const float* __restrict__ gb1,
                const float* __restrict__ gW2,
                const float* __restrict__ gb2,
                float* __restrict__ out,
                int rows)
{
    __shared__ __align__(16) float sC[64 * 132];     // 33792 B
    __shared__ __align__(16) float sW1[20 * 64];     //  5120 B
    __shared__ __align__(16) float sB1[64];
    __shared__ __align__(16) float sW2[64];
    __shared__ __align__(16) float sStat[64 * 20];   //  5120 B, pitch 20
    __shared__ float sQp[4 * 64];                    // per-hidden-quarter partials
    __shared__ float sB2;

    const int tid  = threadIdx.x;
    const int row0 = blockIdx.x * 64;
    const int nr   = min(64, rows - row0);

    // ---------------- stage corners (coalesced float4) ----------------
    {
        const float4* src = (const float4*)(corners + (size_t)row0 * 132);
        float4* dst = (float4*)sC;
        if (nr == 64) {                       // 2112 float4 = 8.25 * 256
            #pragma unroll
            for (int j = 0; j < 8; j++) dst[j * 256 + tid] = src[j * 256 + tid];
            if (tid < 64) dst[2048 + tid] = src[2048 + tid];
        } else {
            int n4 = nr * 33;
            for (int i = tid; i < n4; i += 256) dst[i] = src[i];
        }
    }
    // ---------------- stage weights ----------------
    {
        const float4* w4 = (const float4*)gW1;
        float4* d4 = (float4*)sW1;
        #pragma unroll
        for (int j = 0; j < 2; j++) {
            int idx = j * 256 + tid;
            if (idx < 320) d4[idx] = w4[idx];
        }
        if (tid < 64)        sB1[tid] = gb1[tid];
        else if (tid < 128)  sW2[tid - 64] = gW2[tid - 64];
        if (tid == 0)        sB2 = gb2[0];
    }
    __syncthreads();

    // ---------------- Phase A: one group of 33 per thread, split 17/16 ----------------
    {
        const int lrow = tid >> 2;
        const int g    = tid & 3;
        if (lrow < nr) {
            const float* base = sC + lrow * 132 + 33 * g;

            float sa = 0.f, a0 = 0.f, a1 = 0.f, a2 = 0.f, a3 = 0.f;
            float sb = 0.f, b0 = 0.f, b1v = 0.f, b2v = 0.f, b3 = 0.f;

            #pragma unroll
            for (int k = 0; k < 16; k++) {
                acc_one(base[k],      sa, a0, a1, a2, a3);
                acc_one(base[17 + k], sb, b0, b1v, b2v, b3);
            }
            acc_one(base[16], sa, a0, a1, a2, a3);

            // merge two sorted-desc quads: top4 = sort(max(a_i, b_{3-i}))
            float u0 = fmaxf(a0, b3);
            float u1 = fmaxf(a1, b2v);
            float u2 = fmaxf(a2, b1v);
            float u3 = fmaxf(a3, b0);
            ce(u0, u2); ce(u1, u3); ce(u0, u1); ce(u2, u3);

            float inv = __frcp_rn(sa + sb);
            float p0 = u0 * inv, p1 = u1 * inv, p2 = u2 * inv, p3 = u3 * inv;
            float mean = 0.25f * ((p0 + p1) + (p2 + p3));

            float* so = sStat + lrow * 20 + 5 * g;
            so[0] = p0; so[1] = p1; so[2] = p2; so[3] = p3; so[4] = mean;
        }
    }
    __syncthreads();

    // ---------------- Phase B: MLP ----------------
    {
        const int warp = tid >> 5;
        const int lane = tid & 31;
        const int rh   = warp >> 2;        // row half: 0 or 1
        const int hq   = warp & 3;         // hidden quarter: 0..3
        const int mrow = rh * 32 + lane;

        float st[20];
        {
            const float* sr = sStat + mrow * 20;   // 16B-aligned, conflict-free LDS.128
            float4 q0 = *(const float4*)(sr + 0);
            float4 q1 = *(const float4*)(sr + 4);
            float4 q2 = *(const float4*)(sr + 8);
            float4 q3 = *(const float4*)(sr + 12);
            float4 q4 = *(const float4*)(sr + 16);
            st[0]  = q0.x; st[1]  = q0.y; st[2]  = q0.z; st[3]  = q0.w;
            st[4]  = q1.x; st[5]  = q1.y; st[6]  = q1.z; st[7]  = q1.w;
            st[8]  = q2.x; st[9]  = q2.y; st[10] = q2.z; st[11] = q2.w;
            st[12] = q3.x; st[13] = q3.y; st[14] = q3.z; st[15] = q3.w;
            st[16] = q4.x; st[17] = q4.y; st[18] = q4.z; st[19] = q4.w;
        }

        float q = (hq == 0) ? sB2 : 0.f;
        #pragma unroll
        for (int pass = 0; pass < 2; pass++) {
            const int h0 = hq * 16 + pass * 8;     // warp-uniform
            float acc[8];
            {
                float4 ba = *(const float4*)(sB1 + h0);
                float4 bb = *(const float4*)(sB1 + h0 + 4);
                acc[0] = ba.x; acc[1] = ba.y; acc[2] = ba.z; acc[3] = ba.w;
                acc[4] = bb.x; acc[5] = bb.y; acc[6] = bb.z; acc[7] = bb.w;
            }
            #pragma unroll
            for (int d = 0; d < 20; d++) {
                float sd = st[d];
                float4 wa = *(const float4*)(sW1 + d * 64 + h0);
                float4 wb = *(const float4*)(sW1 + d * 64 + h0 + 4);
                acc[0] += sd * wa.x; acc[1] += sd * wa.y;
                acc[2] += sd * wa.z; acc[3] += sd * wa.w;
                acc[4] += sd * wb.x; acc[5] += sd * wb.y;
                acc[6] += sd * wb.z; acc[7] += sd * wb.w;
            }
            {
                float4 wa = *(const float4*)(sW2 + h0);
                float4 wb = *(const float4*)(sW2 + h0 + 4);
                q += fmaxf(acc[0], 0.f) * wa.x;
                q += fmaxf(acc[1], 0.f) * wa.y;
                q += fmaxf(acc[2], 0.f) * wa.z;
                q += fmaxf(acc[3], 0.f) * wa.w;
                q += fmaxf(acc[4], 0.f) * wb.x;
                q += fmaxf(acc[5], 0.f) * wb.y;
                q += fmaxf(acc[6], 0.f) * wb.z;
                q += fmaxf(acc[7], 0.f) * wb.w;
            }
        }
        sQp[hq * 64 + mrow] = q;
    }
    __syncthreads();

    // ---------------- Phase C: out = scores + q ----------------
    {
        const float4* s4 = (const float4*)(scores + (size_t)row0 * 80);
        float4*       o4 = (float4*)(out + (size_t)row0 * 80);
        if (nr == 64) {                       // 1280 float4 = 5 * 256
            #pragma unroll
            for (int j = 0; j < 5; j++) {
                int i = j * 256 + tid;
                int r = i / 20;
                float qv = (sQp[r] + sQp[64 + r]) + (sQp[128 + r] + sQp[192 + r]);
                float4 v = s4[i];
                v.x += qv; v.y += qv; v.z += qv; v.w += qv;
                o4[i] = v;
            }
        } else {
            int n4 = nr * 20;
            for (int i = tid; i < n4; i += 256) {
                int r = i / 20;
                float qv = (sQp[r] + sQp[64 + r]) + (sQp[128 + r] + sQp[192 + r]);
                float4 v = s4[i];
                v.x += qv; v.y += qv; v.z += qv; v.w += qv;
                o4[i] = v;
            }
        }
    }
}

extern "C" void kernel_launch(void* const* d_in, const int* in_sizes, int n_in,
                              void* d_out, int out_size) {
    const float* scores  = (const float*)d_in[0];
    const float* corners = (const float*)d_in[1];
    const float* W1      = (const float*)d_in[2];
    const float* b1      = (const float*)d_in[3];
    const float* W2      = (const float*)d_in[4];
    const float* b2      = (const float*)d_in[5];
    float* out = (float*)d_out;

    int rows = in_sizes[0] / 80;              // B*L
    int blocks = (rows + 63) / 64;
    lqe_kernel<<<blocks, 256>>>(scores, corners, W1, b1, W2, b2, out, rows);
}